// round 12
// baseline (speedup 1.0000x reference)
#include <cuda_runtime.h>
#include <cuda_fp16.h>
#include <math.h>
#include <stdint.h>

// VanillaLSTM persistent kernel (sm_103 HMMA fp16), split-K warps + dedicated
// sync warp with progressive per-group flags.
// 96 CTAs x 544 threads (16 worker warps + 1 sync warp). h fp16, W fp16.
// Worker warps rw / rw+8 split K (chunks 0-5 / 6-11); partials merged via SMEM
// + 64-thread named barrier. Depth-3 cp.async A pipeline.
// Sync warp polls the 96 (group,row-warp) L2 counters and publishes SMEM flags
// per k-chunk group (RAW gating of issue()) plus an all-ready flag (WAR gating
// of the h store). Workers never touch L2 counters except their own release.

#define ROWS 128
#define HDIM 768
#define SEQ  256
#define NCTA 96
#define NCHUNK 12
#define THREADS 544

// smem layout (bytes)
#define WS_BASE 0                // 12 chunks * 32 rows * 128B (fp16) = 48KB
#define A_BASE 49152             // 16 warps * 3 bufs * 2048 = 96KB
#define FLAG_OFF (A_BASE + 16 * 3 * 2048)     // 147456; flags[0..11]=group, [12]=all
#define SMEM_TOTAL (FLAG_OFF + 128)           // 147584

__device__ __align__(16) __half        g_h[2][ROWS * HDIM];
__device__ __align__(16) float         g_c[ROWS * HDIM];
__device__ __align__(16) __half        g_W[NCTA * NCHUNK * 2048];   // pre-swizzled
__device__ __align__(16) float2        g_wxb[NCTA * 32];
__device__ __align__(128) unsigned     g_ctr[NCHUNK * 8][32];  // (group, row-warp)

// ---------------------------------------------------------------------------
__device__ __forceinline__ uint32_t smem_u32(const void* p) {
    uint32_t a;
    asm("{ .reg .u64 t; cvta.to.shared.u64 t, %1; cvt.u32.u64 %0, t; }" : "=r"(a) : "l"(p));
    return a;
}
__device__ __forceinline__ void cpa16(uint32_t dst, const void* src) {
    asm volatile("cp.async.cg.shared.global [%0], [%1], 16;" :: "r"(dst), "l"(src) : "memory");
}
__device__ __forceinline__ void cp_commit() {
    asm volatile("cp.async.commit_group;" ::: "memory");
}
__device__ __forceinline__ void cp_wait2() {
    asm volatile("cp.async.wait_group 2;" ::: "memory");
}
__device__ __forceinline__ void cp_wait1() {
    asm volatile("cp.async.wait_group 1;" ::: "memory");
}
__device__ __forceinline__ void cp_wait0() {
    asm volatile("cp.async.wait_group 0;" ::: "memory");
}
__device__ __forceinline__ void ldsm4(uint32_t* r, uint32_t addr) {
    asm volatile("ldmatrix.sync.aligned.m8n8.x4.shared.b16 {%0,%1,%2,%3}, [%4];"
                 : "=r"(r[0]), "=r"(r[1]), "=r"(r[2]), "=r"(r[3]) : "r"(addr));
}
__device__ __forceinline__ void mma_f16(float* d, const uint32_t* a, uint32_t b0, uint32_t b1) {
    asm volatile(
        "mma.sync.aligned.m16n8k16.row.col.f32.f16.f16.f32 "
        "{%0,%1,%2,%3}, {%4,%5,%6,%7}, {%8,%9}, {%0,%1,%2,%3};"
        : "+f"(d[0]), "+f"(d[1]), "+f"(d[2]), "+f"(d[3])
        : "r"(a[0]), "r"(a[1]), "r"(a[2]), "r"(a[3]), "r"(b0), "r"(b1));
}
__device__ __forceinline__ unsigned ld_acq_gpu(const unsigned* p) {
    unsigned v;
    asm volatile("ld.acquire.gpu.global.u32 %0, [%1];" : "=r"(v) : "l"(p) : "memory");
    return v;
}

// ---------------------------------------------------------------------------
__global__ void init_state(const float* __restrict__ h0, const float* __restrict__ c0) {
    int i = blockIdx.x * 256 + threadIdx.x;
    if (i < NCHUNK * 8) g_ctr[i][0] = 0u;
    if (i < ROWS * HDIM) {
        g_h[0][i] = __float2half(h0[i]);
        g_c[i] = c0[i];
    }
}

// ---------------------------------------------------------------------------
__global__ void repack(const float* __restrict__ Wi, const float* __restrict__ Wf,
                       const float* __restrict__ Wc, const float* __restrict__ Wo,
                       const float* __restrict__ bi, const float* __restrict__ bf,
                       const float* __restrict__ bc, const float* __restrict__ bo) {
    int idx = blockIdx.x * 256 + threadIdx.x;
    const int TOT = NCTA * NCHUNK * 2048;
    if (idx < TOT) {
        int kl  = idx & 63;
        int n   = (idx >> 6) & 31;
        int blk = idx >> 11;
        int kc  = blk % NCHUNK;
        int nb  = blk / NCHUNK;
        int gate = n & 3;
        int j = nb * 8 + (n >> 2);
        const float* W = (gate == 0) ? Wi : (gate == 1) ? Wf : (gate == 2) ? Wc : Wo;
        float v = W[(1 + kc * 64 + kl) * HDIM + j];
        int dst = blk * 2048 + n * 64 + (((kl >> 3) ^ (n & 7)) << 3) + (kl & 7);
        g_W[dst] = __float2half(v);
    }
    if (idx < NCTA * 32) {
        int n = idx & 31;
        int nb = idx >> 5;
        int gate = n & 3;
        int j = nb * 8 + (n >> 2);
        const float* W = (gate == 0) ? Wi : (gate == 1) ? Wf : (gate == 2) ? Wc : Wo;
        const float* B = (gate == 0) ? bi : (gate == 1) ? bf : (gate == 2) ? bc : bo;
        g_wxb[idx] = make_float2(W[j], B[j]);
    }
}

// ---------------------------------------------------------------------------
__global__ void __launch_bounds__(THREADS, 1) lstm_persistent(const float* __restrict__ x) {
    extern __shared__ char smem[];
    const uint32_t sb = smem_u32(smem);
    const int tid = threadIdx.x;
    const int lane = tid & 31, wid = tid >> 5;
    const int nb = blockIdx.x;
    const uint32_t flag_base = sb + FLAG_OFF;

    // ---------------- prologue: stage W into smem ----------------
    {
        const uint4* __restrict__ sw = ((const uint4*)g_W) + nb * 3072;
        uint4* dw = (uint4*)(smem + WS_BASE);
        for (int i = tid; i < 3072; i += THREADS) dw[i] = sw[i];
        if (tid < 13) *(volatile unsigned*)(smem + FLAG_OFF + tid * 4) = 0u;
    }
    __syncthreads();

    // ======================= SYNC WARP =======================
    if (wid == 16) {
        // lanes 0..23: pair (2g, 2g+1) covers group g; 4 counters per lane
        const int g = lane >> 1;
        const int rwb = (lane & 1) * 4;
        const unsigned* p0 = (lane < 24) ? &g_ctr[g * 8 + rwb + 0][0] : &g_ctr[0][0];
        const unsigned* p1 = (lane < 24) ? &g_ctr[g * 8 + rwb + 1][0] : &g_ctr[0][0];
        const unsigned* p2 = (lane < 24) ? &g_ctr[g * 8 + rwb + 2][0] : &g_ctr[0][0];
        const unsigned* p3 = (lane < 24) ? &g_ctr[g * 8 + rwb + 3][0] : &g_ctr[0][0];
        for (int t = 1; t < SEQ; ++t) {
            const unsigned tgt = 16u * (unsigned)t;
            for (;;) {
                bool ok = true;
                if (lane < 24) {
                    ok = (ld_acq_gpu(p0) >= tgt) && (ld_acq_gpu(p1) >= tgt) &&
                         (ld_acq_gpu(p2) >= tgt) && (ld_acq_gpu(p3) >= tgt);
                }
                unsigned bal = __ballot_sync(0xffffffffu, ok);
                unsigned pairs = bal & (bal >> 1);          // bit 2g set if group g ready
                if (lane < 24 && !(lane & 1) && ((pairs >> lane) & 1u)) {
                    asm volatile("st.release.cta.shared.u32 [%0], %1;"
                                 :: "r"(flag_base + (uint32_t)g * 4), "r"((unsigned)t)
                                 : "memory");
                }
                if ((pairs & 0x00555555u) == 0x00555555u) break;
            }
            if (lane == 0) {
                asm volatile("st.release.cta.shared.u32 [%0], %1;"
                             :: "r"(flag_base + 48u), "r"((unsigned)t) : "memory");
            }
            __syncwarp();
        }
        return;
    }

    // ======================= WORKER WARPS =======================
    const int rw = wid & 7;          // row-warp: rows [16rw, 16rw+16)
    const int hf = wid >> 3;         // K-half: chunks [6hf, 6hf+6)
    const uint32_t abase = sb + A_BASE + (uint32_t)wid * 6144;  // 3 bufs x 2048

    // ldsm lane constants (XOR swizzle, pitch 128)
    const int sel = lane >> 3, li = lane & 7;
    const int hsA = sel >> 1, hsB = sel & 1;
    const uint32_t aoffrow = (uint32_t)((li + (sel & 1) * 8) * 128);
    const uint32_t boffrow = (uint32_t)((li + (sel >> 1) * 8) * 128);

    // epilogue constants
    const int my_row = rw * 16 + (lane >> 2) + (lane & 1) * 8;
    const float* __restrict__ xrow = x + (my_row >> 1) * 512 + (my_row & 1);
    const int ntK = (hf == 0) ? 0 : 2;    // kept n-tiles
    const int ntS = 2 - ntK;              // sent n-tiles

    float2 wxi[2], wxf[2], wxc[2], wxo[2];
    float  creg[2];
    {
        const float2* __restrict__ wxbp = g_wxb + nb * 32;
#pragma unroll
        for (int q = 0; q < 2; ++q) {
            int jl = (ntK + q) * 2 + ((lane & 3) >> 1);
            wxi[q] = wxbp[4 * jl + 0];
            wxf[q] = wxbp[4 * jl + 1];
            wxc[q] = wxbp[4 * jl + 2];
            wxo[q] = wxbp[4 * jl + 3];
            creg[q] = g_c[my_row * HDIM + nb * 8 + jl];
        }
    }

    unsigned* __restrict__ relp = &g_ctr[(nb >> 3) * 8 + rw][0];

    // SMEM flag spin (acquire.cta: chained after sync warp's gpu-acquire)
    auto waitflag = [&](int idx, unsigned t) {
        const uint32_t fa = flag_base + (uint32_t)idx * 4;
        unsigned v;
        do {
            asm volatile("ld.acquire.cta.shared.u32 %0, [%1];"
                         : "=r"(v) : "r"(fa) : "memory");
        } while (v < t);
    };

    for (int t = 0; t < SEQ; ++t) {
        const int par = t & 1;
        const __half* __restrict__ hin = g_h[par];
        __half* __restrict__ hout = g_h[par ^ 1];
        const unsigned ut = (unsigned)t;

        float d[4][4];
#pragma unroll
        for (int i = 0; i < 4; i++)
#pragma unroll
            for (int k = 0; k < 4; k++) d[i][k] = 0.f;

        // per-warp A staging: chunk group g = hf*6+l; gate on flags[g]
        auto issue = [&](int l) {
            const int g = hf * 6 + l;
            if (t > 0) waitflag(g, ut);
            const uint32_t bufs = abase + (uint32_t)(l % 3) * 2048;
#pragma unroll
            for (int i = 0; i < 4; ++i) {
                int o = lane * 4 + i;            // 0..127
                int row = o >> 3, seg = o & 7;
                uint32_t dst = bufs + (uint32_t)(row * 128 + ((seg ^ (row & 7)) << 4));
                cpa16(dst, hin + (rw * 16 + row) * HDIM + g * 64 + seg * 8);
            }
            cp_commit();
        };

        issue(0); issue(1); issue(2);

#pragma unroll
        for (int l = 0; l < 6; ++l) {
            if (l < 4)       cp_wait2();
            else if (l == 4) cp_wait1();
            else             cp_wait0();
            __syncwarp();
            const int g = hf * 6 + l;
            const uint32_t abuf = abase + (uint32_t)(l % 3) * 2048;
            const uint32_t wch = sb + WS_BASE + (uint32_t)g * 4096;
#pragma unroll
            for (int ks = 0; ks < 4; ++ks) {
                const uint32_t asw = (uint32_t)((((ks << 1) | hsA) ^ li) << 4);
                const uint32_t bsw = (uint32_t)((((ks << 1) | hsB) ^ li) << 4);
                uint32_t a[4];
                ldsm4(a, abuf + aoffrow + asw);
#pragma unroll
                for (int p = 0; p < 2; ++p) {
                    uint32_t b[4];
                    ldsm4(b, wch + boffrow + (uint32_t)(p * 2048) + bsw);
                    mma_f16(d[2 * p],     a, b[0], b[1]);
                    mma_f16(d[2 * p + 1], a, b[2], b[3]);
                }
            }
            __syncwarp();
            if (l + 3 < 6) issue(l + 3);
        }

        // WAR gate: all readers of the buffer we're about to overwrite are done
        if (t > 0) waitflag(12, ut);

        // ---------------- split-K partial exchange (warp pair rw, rw+8) -------
        {
            float* ex = (float*)(smem + A_BASE + wid * 6144 + lane * 32);
#pragma unroll
            for (int k = 0; k < 4; ++k) { ex[k] = d[ntS][k]; ex[4 + k] = d[ntS + 1][k]; }
            asm volatile("bar.sync %0, 64;" :: "r"(1 + rw) : "memory");
            const float* px = (const float*)(smem + A_BASE + (wid ^ 8) * 6144 + lane * 32);
#pragma unroll
            for (int k = 0; k < 4; ++k) { d[ntK][k] += px[k]; d[ntK + 1][k] += px[4 + k]; }
            asm volatile("bar.sync %0, 64;" :: "r"(1 + rw) : "memory");
        }

        // ---------------- fused LSTM epilogue (kept n-tiles) ------------------
        const float xv = xrow[2 * t];
#pragma unroll
        for (int q = 0; q < 2; ++q) {
            const int nt = ntK + q;
            const int jl = nt * 2 + ((lane & 3) >> 1);
            float p0 = __shfl_xor_sync(0xffffffffu, d[nt][0], 1);
            float p1 = __shfl_xor_sync(0xffffffffu, d[nt][1], 1);
            float p2 = __shfl_xor_sync(0xffffffffu, d[nt][2], 1);
            float p3 = __shfl_xor_sync(0xffffffffu, d[nt][3], 1);
            float gi, gf, gc, go;
            if (!(lane & 1)) { gi = d[nt][0]; gf = d[nt][1]; gc = p0; go = p1; }
            else             { gi = p2;       gf = p3;       gc = d[nt][2]; go = d[nt][3]; }
            float pi = gi + xv * wxi[q].x + wxi[q].y;
            float pf = gf + xv * wxf[q].x + wxf[q].y;
            float pc = gc + xv * wxc[q].x + wxc[q].y;
            float po = go + xv * wxo[q].x + wxo[q].y;
            float ig = __fdividef(1.f, 1.f + __expf(-pi));
            float fg = __fdividef(1.f, 1.f + __expf(-pf));
            float thc = 1.f - __fdividef(2.f, 1.f + __expf(2.f * pc));
            float cn = fg * creg[q] + ig * thc;
            float thn = 1.f - __fdividef(2.f, 1.f + __expf(2.f * cn));
            float hn = po * thn;            // no sigmoid on output gate
            creg[q] = cn;
            hout[my_row * HDIM + nb * 8 + jl] = __float2half(hn);
        }

        // publish (release orders prior stores)
        if (t + 1 < SEQ) {
            __syncwarp();
            if (lane == 0) {
                asm volatile("red.release.gpu.global.add.u32 [%0], %1;"
                             :: "l"(relp), "r"(1u) : "memory");
            }
        }
    }
}

// ---------------------------------------------------------------------------
__global__ void out_final(const float* __restrict__ Wout,
                          const float* __restrict__ bout,
                          float* __restrict__ out) {
    int gtid = blockIdx.x * 128 + threadIdx.x;
    int r = gtid >> 5, lane = gtid & 31;
    float s = 0.f;
    for (int k = lane; k < HDIM; k += 32)
        s += __half2float(g_h[0][r * HDIM + k]) * Wout[k];
#pragma unroll
    for (int o = 16; o; o >>= 1) s += __shfl_xor_sync(0xffffffffu, s, o);
    if (lane == 0) out[r] = s + bout[0];
}

// ---------------------------------------------------------------------------
extern "C" void kernel_launch(void* const* d_in, const int* in_sizes, int n_in,
                              void* d_out, int out_size) {
    (void)in_sizes; (void)n_in; (void)out_size;
    const float* x    = (const float*)d_in[0];
    const float* h0   = (const float*)d_in[1];
    const float* c0   = (const float*)d_in[2];
    const float* Wi   = (const float*)d_in[3];
    const float* bi   = (const float*)d_in[4];
    const float* Wf   = (const float*)d_in[5];
    const float* bf   = (const float*)d_in[6];
    const float* Wc   = (const float*)d_in[7];
    const float* bc   = (const float*)d_in[8];
    const float* Wo   = (const float*)d_in[9];
    const float* bo   = (const float*)d_in[10];
    const float* Wout = (const float*)d_in[11];
    const float* bout = (const float*)d_in[12];
    float* out = (float*)d_out;

    static int configured = 0;
    if (!configured) {
        cudaFuncSetAttribute(lstm_persistent,
                             cudaFuncAttributeMaxDynamicSharedMemorySize, SMEM_TOTAL);
        configured = 1;
    }

    init_state<<<(ROWS * HDIM + 255) / 256, 256>>>(h0, c0);
    repack<<<(NCTA * NCHUNK * 2048 + 255) / 256, 256>>>(Wi, Wf, Wc, Wo, bi, bf, bc, bo);
    lstm_persistent<<<NCTA, THREADS, SMEM_TOTAL>>>(x);
    out_final<<<32, 128>>>(Wout, bout, out);
}

// round 13
// speedup vs baseline: 1.4388x; 1.4388x over previous
#include <cuda_runtime.h>
#include <cuda_fp16.h>
#include <math.h>
#include <stdint.h>

// VanillaLSTM persistent kernel (sm_103 HMMA fp16 single-W), split-K warps.
// 96 CTAs x 512 threads. h fp16, W fp16. Warps rw / rw+8 split K (chunks 0-5 /
// 6-11), partials merged via SMEM + 64-thread named barrier. Depth-3 cp.async
// A pipeline. Dataflow sync, coarse: 12 per-CTA-group counters, ONE release
// per CTA per step (after __syncthreads), warp 0 polls 12 counters once and
// publishes a SMEM flag; other warps spin on the flag.

#define ROWS 128
#define HDIM 768
#define SEQ  256
#define NCTA 96
#define NCHUNK 12

// smem layout (bytes)
#define WS_BASE 0                // 12 chunks * 32 rows * 128B (fp16) = 48KB
#define A_BASE 49152             // 16 warps * 3 bufs * 2048 = 96KB
#define FLAG_OFF (A_BASE + 16 * 3 * 2048)     // 147456
#define SMEM_TOTAL (FLAG_OFF + 128)           // 147584

__device__ __align__(16) __half        g_h[2][ROWS * HDIM];
__device__ __align__(16) float         g_c[ROWS * HDIM];
__device__ __align__(16) __half        g_W[NCTA * NCHUNK * 2048];   // pre-swizzled
__device__ __align__(16) float2        g_wxb[NCTA * 32];
__device__ __align__(128) unsigned     g_ctr[NCHUNK][32];   // one per CTA group

// ---------------------------------------------------------------------------
__device__ __forceinline__ uint32_t smem_u32(const void* p) {
    uint32_t a;
    asm("{ .reg .u64 t; cvta.to.shared.u64 t, %1; cvt.u32.u64 %0, t; }" : "=r"(a) : "l"(p));
    return a;
}
__device__ __forceinline__ void cpa16(uint32_t dst, const void* src) {
    asm volatile("cp.async.cg.shared.global [%0], [%1], 16;" :: "r"(dst), "l"(src) : "memory");
}
__device__ __forceinline__ void cp_commit() {
    asm volatile("cp.async.commit_group;" ::: "memory");
}
__device__ __forceinline__ void cp_wait2() {
    asm volatile("cp.async.wait_group 2;" ::: "memory");
}
__device__ __forceinline__ void cp_wait1() {
    asm volatile("cp.async.wait_group 1;" ::: "memory");
}
__device__ __forceinline__ void cp_wait0() {
    asm volatile("cp.async.wait_group 0;" ::: "memory");
}
__device__ __forceinline__ void ldsm4(uint32_t* r, uint32_t addr) {
    asm volatile("ldmatrix.sync.aligned.m8n8.x4.shared.b16 {%0,%1,%2,%3}, [%4];"
                 : "=r"(r[0]), "=r"(r[1]), "=r"(r[2]), "=r"(r[3]) : "r"(addr));
}
__device__ __forceinline__ void mma_f16(float* d, const uint32_t* a, uint32_t b0, uint32_t b1) {
    asm volatile(
        "mma.sync.aligned.m16n8k16.row.col.f32.f16.f16.f32 "
        "{%0,%1,%2,%3}, {%4,%5,%6,%7}, {%8,%9}, {%0,%1,%2,%3};"
        : "+f"(d[0]), "+f"(d[1]), "+f"(d[2]), "+f"(d[3])
        : "r"(a[0]), "r"(a[1]), "r"(a[2]), "r"(a[3]), "r"(b0), "r"(b1));
}

// ---------------------------------------------------------------------------
__global__ void init_state(const float* __restrict__ h0, const float* __restrict__ c0) {
    int i = blockIdx.x * 256 + threadIdx.x;
    if (i < NCHUNK) g_ctr[i][0] = 0u;
    if (i < ROWS * HDIM) {
        g_h[0][i] = __float2half(h0[i]);
        g_c[i] = c0[i];
    }
}

// ---------------------------------------------------------------------------
// Repack weights pre-swizzled fp16: elem (blk, n, kl) ->
//   blk*2048 + n*64 + ((kl>>3) ^ (n&7))*8 + (kl&7)
__global__ void repack(const float* __restrict__ Wi, const float* __restrict__ Wf,
                       const float* __restrict__ Wc, const float* __restrict__ Wo,
                       const float* __restrict__ bi, const float* __restrict__ bf,
                       const float* __restrict__ bc, const float* __restrict__ bo) {
    int idx = blockIdx.x * 256 + threadIdx.x;
    const int TOT = NCTA * NCHUNK * 2048;
    if (idx < TOT) {
        int kl  = idx & 63;
        int n   = (idx >> 6) & 31;
        int blk = idx >> 11;
        int kc  = blk % NCHUNK;
        int nb  = blk / NCHUNK;
        int gate = n & 3;
        int j = nb * 8 + (n >> 2);
        const float* W = (gate == 0) ? Wi : (gate == 1) ? Wf : (gate == 2) ? Wc : Wo;
        float v = W[(1 + kc * 64 + kl) * HDIM + j];
        int dst = blk * 2048 + n * 64 + (((kl >> 3) ^ (n & 7)) << 3) + (kl & 7);
        g_W[dst] = __float2half(v);
    }
    if (idx < NCTA * 32) {
        int n = idx & 31;
        int nb = idx >> 5;
        int gate = n & 3;
        int j = nb * 8 + (n >> 2);
        const float* W = (gate == 0) ? Wi : (gate == 1) ? Wf : (gate == 2) ? Wc : Wo;
        const float* B = (gate == 0) ? bi : (gate == 1) ? bf : (gate == 2) ? bc : bo;
        g_wxb[idx] = make_float2(W[j], B[j]);
    }
}

// ---------------------------------------------------------------------------
__global__ void __launch_bounds__(512, 1) lstm_persistent(const float* __restrict__ x) {
    extern __shared__ char smem[];
    const uint32_t sb = smem_u32(smem);
    const int tid = threadIdx.x;
    const int lane = tid & 31, wid = tid >> 5;
    const int rw = wid & 7;          // row-warp: rows [16rw, 16rw+16)
    const int hf = wid >> 3;         // K-half: chunks [6hf, 6hf+6)
    const int nb = blockIdx.x;
    const uint32_t flag_addr = sb + FLAG_OFF;

    // ---------------- prologue: stage W into smem (contiguous, pre-swizzled) --
    {
        const uint4* __restrict__ sw = ((const uint4*)g_W) + nb * 3072;
        uint4* dw = (uint4*)(smem + WS_BASE);
        for (int i = tid; i < 3072; i += 512) dw[i] = sw[i];
        if (tid == 0) *(volatile unsigned*)(smem + FLAG_OFF) = 0u;
    }
    __syncthreads();

    const uint32_t abase = sb + A_BASE + (uint32_t)wid * 6144;  // 3 bufs x 2048

    // ldsm lane constants (XOR swizzle, pitch 128)
    const int sel = lane >> 3, li = lane & 7;
    const int hsA = sel >> 1, hsB = sel & 1;
    const uint32_t aoffrow = (uint32_t)((li + (sel & 1) * 8) * 128);
    const uint32_t boffrow = (uint32_t)((li + (sel >> 1) * 8) * 128);

    // epilogue constants
    const int my_row = rw * 16 + (lane >> 2) + (lane & 1) * 8;
    const float* __restrict__ xrow = x + (my_row >> 1) * 512 + (my_row & 1);
    const int ntK = (hf == 0) ? 0 : 2;    // kept n-tiles
    const int ntS = 2 - ntK;              // sent n-tiles

    // registers: wxb + cell state for kept n-tiles
    float2 wxi[2], wxf[2], wxc[2], wxo[2];
    float  creg[2];
    {
        const float2* __restrict__ wxbp = g_wxb + nb * 32;
#pragma unroll
        for (int q = 0; q < 2; ++q) {
            int jl = (ntK + q) * 2 + ((lane & 3) >> 1);
            wxi[q] = wxbp[4 * jl + 0];
            wxf[q] = wxbp[4 * jl + 1];
            wxc[q] = wxbp[4 * jl + 2];
            wxo[q] = wxbp[4 * jl + 3];
            creg[q] = g_c[my_row * HDIM + nb * 8 + jl];
        }
    }

    // sync: ONE counter per CTA group (12). Warp 0 lanes 0-11 poll, lane 0
    // publishes flag; workers spin on SMEM flag. One release per CTA per step.
    unsigned* __restrict__ relp = &g_ctr[nb >> 3][0];
    const unsigned* __restrict__ pollp =
        (lane < NCHUNK) ? &g_ctr[lane][0] : &g_ctr[0][0];

    for (int t = 0; t < SEQ; ++t) {
        const int par = t & 1;
        const __half* __restrict__ hin = g_h[par];
        __half* __restrict__ hout = g_h[par ^ 1];

        // ---- dataflow wait ----
        if (t > 0) {
            const unsigned tgt = 8u * (unsigned)t;
            if (wid == 0) {
                for (;;) {
                    unsigned v = tgt;
                    if (lane < NCHUNK) {
                        asm volatile("ld.acquire.gpu.global.u32 %0, [%1];"
                                     : "=r"(v) : "l"(pollp) : "memory");
                    }
                    if (__all_sync(0xffffffffu, v >= tgt)) break;
                }
                if (lane == 0) {
                    asm volatile("st.release.cta.shared.u32 [%0], %1;"
                                 :: "r"(flag_addr), "r"((unsigned)t) : "memory");
                }
                __syncwarp();
            } else {
                unsigned v;
                do {
                    asm volatile("ld.acquire.cta.shared.u32 %0, [%1];"
                                 : "=r"(v) : "r"(flag_addr) : "memory");
                } while (v < (unsigned)t);
            }
        }
        __syncwarp();

        float d[4][4];
#pragma unroll
        for (int i = 0; i < 4; i++)
#pragma unroll
            for (int k = 0; k < 4; k++) d[i][k] = 0.f;

        // per-warp A staging: 16 rows x 64 k fp16, XOR swizzle, buffer l%3
        auto issue = [&](int l) {
            const int g = hf * 6 + l;
            const uint32_t bufs = abase + (uint32_t)(l % 3) * 2048;
#pragma unroll
            for (int i = 0; i < 4; ++i) {
                int o = lane * 4 + i;            // 0..127
                int row = o >> 3, seg = o & 7;
                uint32_t dst = bufs + (uint32_t)(row * 128 + ((seg ^ (row & 7)) << 4));
                cpa16(dst, hin + (rw * 16 + row) * HDIM + g * 64 + seg * 8);
            }
            cp_commit();
        };

        issue(0); issue(1); issue(2);

#pragma unroll
        for (int l = 0; l < 6; ++l) {
            if (l < 4)       cp_wait2();
            else if (l == 4) cp_wait1();
            else             cp_wait0();
            __syncwarp();
            const int g = hf * 6 + l;
            const uint32_t abuf = abase + (uint32_t)(l % 3) * 2048;
            const uint32_t wch = sb + WS_BASE + (uint32_t)g * 4096;
#pragma unroll
            for (int ks = 0; ks < 4; ++ks) {
                const uint32_t asw = (uint32_t)((((ks << 1) | hsA) ^ li) << 4);
                const uint32_t bsw = (uint32_t)((((ks << 1) | hsB) ^ li) << 4);
                uint32_t a[4];
                ldsm4(a, abuf + aoffrow + asw);
#pragma unroll
                for (int p = 0; p < 2; ++p) {
                    uint32_t b[4];
                    ldsm4(b, wch + boffrow + (uint32_t)(p * 2048) + bsw);
                    mma_f16(d[2 * p],     a, b[0], b[1]);
                    mma_f16(d[2 * p + 1], a, b[2], b[3]);
                }
            }
            __syncwarp();
            if (l + 3 < 6) issue(l + 3);
        }

        // ---------------- split-K partial exchange (warp pair rw, rw+8) -------
        {
            float* ex = (float*)(smem + A_BASE + wid * 6144 + lane * 32);
#pragma unroll
            for (int k = 0; k < 4; ++k) { ex[k] = d[ntS][k]; ex[4 + k] = d[ntS + 1][k]; }
            asm volatile("bar.sync %0, 64;" :: "r"(1 + rw) : "memory");
            const float* px = (const float*)(smem + A_BASE + (wid ^ 8) * 6144 + lane * 32);
#pragma unroll
            for (int k = 0; k < 4; ++k) { d[ntK][k] += px[k]; d[ntK + 1][k] += px[4 + k]; }
            asm volatile("bar.sync %0, 64;" :: "r"(1 + rw) : "memory");
        }

        // ---------------- fused LSTM epilogue (kept n-tiles) ------------------
        const float xv = xrow[2 * t];
#pragma unroll
        for (int q = 0; q < 2; ++q) {
            const int nt = ntK + q;
            const int jl = nt * 2 + ((lane & 3) >> 1);
            float p0 = __shfl_xor_sync(0xffffffffu, d[nt][0], 1);
            float p1 = __shfl_xor_sync(0xffffffffu, d[nt][1], 1);
            float p2 = __shfl_xor_sync(0xffffffffu, d[nt][2], 1);
            float p3 = __shfl_xor_sync(0xffffffffu, d[nt][3], 1);
            float gi, gf, gc, go;
            if (!(lane & 1)) { gi = d[nt][0]; gf = d[nt][1]; gc = p0; go = p1; }
            else             { gi = p2;       gf = p3;       gc = d[nt][2]; go = d[nt][3]; }
            float pi = gi + xv * wxi[q].x + wxi[q].y;
            float pf = gf + xv * wxf[q].x + wxf[q].y;
            float pc = gc + xv * wxc[q].x + wxc[q].y;
            float po = go + xv * wxo[q].x + wxo[q].y;
            float ig = __fdividef(1.f, 1.f + __expf(-pi));
            float fg = __fdividef(1.f, 1.f + __expf(-pf));
            float thc = 1.f - __fdividef(2.f, 1.f + __expf(2.f * pc));
            float cn = fg * creg[q] + ig * thc;
            float thn = 1.f - __fdividef(2.f, 1.f + __expf(2.f * cn));
            float hn = po * thn;            // no sigmoid on output gate
            creg[q] = cn;
            hout[my_row * HDIM + nb * 8 + jl] = __float2half(hn);
        }

        // publish: CTA-wide sync orders all warps' h stores before the single
        // release-add by thread 0 (standard message-passing idiom).
        if (t + 1 < SEQ) {
            __syncthreads();
            if (tid == 0) {
                asm volatile("red.release.gpu.global.add.u32 [%0], %1;"
                             :: "l"(relp), "r"(1u) : "memory");
            }
        }
    }
}

// ---------------------------------------------------------------------------
__global__ void out_final(const float* __restrict__ Wout,
                          const float* __restrict__ bout,
                          float* __restrict__ out) {
    int gtid = blockIdx.x * 128 + threadIdx.x;
    int r = gtid >> 5, lane = gtid & 31;
    float s = 0.f;
    for (int k = lane; k < HDIM; k += 32)
        s += __half2float(g_h[0][r * HDIM + k]) * Wout[k];
#pragma unroll
    for (int o = 16; o; o >>= 1) s += __shfl_xor_sync(0xffffffffu, s, o);
    if (lane == 0) out[r] = s + bout[0];
}

// ---------------------------------------------------------------------------
extern "C" void kernel_launch(void* const* d_in, const int* in_sizes, int n_in,
                              void* d_out, int out_size) {
    (void)in_sizes; (void)n_in; (void)out_size;
    const float* x    = (const float*)d_in[0];
    const float* h0   = (const float*)d_in[1];
    const float* c0   = (const float*)d_in[2];
    const float* Wi   = (const float*)d_in[3];
    const float* bi   = (const float*)d_in[4];
    const float* Wf   = (const float*)d_in[5];
    const float* bf   = (const float*)d_in[6];
    const float* Wc   = (const float*)d_in[7];
    const float* bc   = (const float*)d_in[8];
    const float* Wo   = (const float*)d_in[9];
    const float* bo   = (const float*)d_in[10];
    const float* Wout = (const float*)d_in[11];
    const float* bout = (const float*)d_in[12];
    float* out = (float*)d_out;

    static int configured = 0;
    if (!configured) {
        cudaFuncSetAttribute(lstm_persistent,
                             cudaFuncAttributeMaxDynamicSharedMemorySize, SMEM_TOTAL);
        configured = 1;
    }

    init_state<<<(ROWS * HDIM + 255) / 256, 256>>>(h0, c0);
    repack<<<(NCTA * NCHUNK * 2048 + 255) / 256, 256>>>(Wi, Wf, Wc, Wo, bi, bf, bc, bo);
    lstm_persistent<<<NCTA, 512, SMEM_TOTAL>>>(x);
    out_final<<<32, 128>>>(Wout, bout, out);
}